// round 13
// baseline (speedup 1.0000x reference)
#include <cuda_runtime.h>
#include <cuda.h>
#include <cuda_fp16.h>
#include <cstdint>

// Problem constants
#define BATCH     32768
#define DIM       512
#define NUM_STEPS 100
#define NTOT      (BATCH * DIM)       // 2^24 elements
#define HALF_ELEMS (NTOT / 2)         // 2^23 (half-batch elements)

#define G_CTAS    512                 // half-batch GEMM CTAs (128 m x 4 n)
#define E_CTAS    4096                // half-batch epilogue CTAs (2048 elem each)
#define FAT_CTAS  (G_CTAS + E_CTAS)

// ---------------------------------------------------------------------------
// Device scratch (no runtime allocation allowed)
// ---------------------------------------------------------------------------
__device__ __half g_hi0[NTOT];
__device__ __half g_lo0[NTOT];
__device__ __half g_hi1[NTOT];
__device__ __half g_lo1[NTOT];
__device__ float  g_score[NTOT];      // per-step GEMM result (f32)
__device__ __half g_Bhi[DIM * DIM];   // W_top^T [n][k] (fp16)
__device__ float  g_s[DIM];           // s[j] = sum_k W_bot[k][j]

// ---------------------------------------------------------------------------
// PTX helpers (sm_90-baseline: TMA bulk + mbarrier; NO 'a'-gated instrs)
// ---------------------------------------------------------------------------
__device__ __forceinline__ uint32_t smem_u32(const void* p) {
    uint32_t a;
    asm("{ .reg .u64 t; cvta.to.shared.u64 t, %1; cvt.u32.u64 %0, t; }"
        : "=r"(a) : "l"(p));
    return a;
}

#define MBARRIER_INIT(addr, cnt) \
    asm volatile("mbarrier.init.shared.b64 [%0], %1;" \
                 :: "r"((uint32_t)(addr)), "r"((uint32_t)(cnt)) : "memory")

#define MBARRIER_EXPECT_TX(addr, bytes) \
    asm volatile("mbarrier.arrive.expect_tx.shared.b64 _, [%0], %1;" \
                 :: "r"((uint32_t)(addr)), "r"((uint32_t)(bytes)) : "memory")

#define MBARRIER_ARRIVE(addr) \
    asm volatile("mbarrier.arrive.shared.b64 _, [%0];" \
                 :: "r"((uint32_t)(addr)) : "memory")

#define MBARRIER_WAIT_PARITY(addr, parity) do { \
    uint32_t _m = (uint32_t)(addr); \
    uint32_t _p = (uint32_t)(parity); \
    uint32_t _d; \
    asm volatile("{\n\t.reg .pred p;\n\t" \
        "mbarrier.try_wait.parity.acquire.cta.shared::cta.b64 p, [%1], %2;\n\t" \
        "selp.b32 %0, 1, 0, p;\n\t}" : "=r"(_d) : "r"(_m), "r"(_p) : "memory"); \
    if (!_d) { \
        asm volatile("{\n\t.reg .pred P1;\n\t" \
            "WL_%=:\n\t" \
            "mbarrier.try_wait.parity.acquire.cta.shared::cta.b64 P1, [%0], %1, 0x989680;\n\t" \
            "@P1 bra.uni WD_%=;\n\t" \
            "bra.uni WL_%=;\n\t" \
            "WD_%=:\n\t}" :: "r"(_m), "r"(_p) : "memory"); \
    } \
} while (0)

__device__ __forceinline__ void tma_load_2d(uint32_t smem_addr, const void* map,
                                            int cx, int cy, uint32_t mbar) {
    asm volatile(
        "cp.async.bulk.tensor.2d.shared::cta.global.tile.mbarrier::complete_tx::bytes "
        "[%0], [%1, {%2, %3}], [%4];"
        :: "r"(smem_addr), "l"(map), "r"(cx), "r"(cy), "r"(mbar) : "memory");
}

__device__ __forceinline__ void ldsm4(uint32_t* r, uint32_t addr) {
    asm volatile("ldmatrix.sync.aligned.m8n8.x4.shared.b16 {%0,%1,%2,%3}, [%4];"
                 : "=r"(r[0]), "=r"(r[1]), "=r"(r[2]), "=r"(r[3]) : "r"(addr));
}

__device__ __forceinline__ void mma16816(float* d, const uint32_t* a,
                                         const uint32_t* b) {
    asm volatile(
        "mma.sync.aligned.m16n8k16.row.col.f32.f16.f16.f32 "
        "{%0,%1,%2,%3}, {%4,%5,%6,%7}, {%8,%9}, {%0,%1,%2,%3};"
        : "+f"(d[0]), "+f"(d[1]), "+f"(d[2]), "+f"(d[3])
        : "r"(a[0]), "r"(a[1]), "r"(a[2]), "r"(a[3]), "r"(b[0]), "r"(b[1]));
}

// ---------------------------------------------------------------------------
// Threefry-2x32 (20 rounds) + JAX normal — verified rounds 3/6/7/9/11
// ---------------------------------------------------------------------------
#define TF_ROUND(r) { x0 += x1; x1 = __funnelshift_l(x1, x1, (r)); x1 ^= x0; }

__device__ __forceinline__ void tf2x32(uint32_t k0, uint32_t k1,
                                       uint32_t x0, uint32_t x1,
                                       uint32_t& o0, uint32_t& o1) {
    uint32_t k2 = k0 ^ k1 ^ 0x1BD11BDAu;
    x0 += k0; x1 += k1;
    TF_ROUND(13) TF_ROUND(15) TF_ROUND(26) TF_ROUND(6)
    x0 += k1; x1 += k2 + 1u;
    TF_ROUND(17) TF_ROUND(29) TF_ROUND(16) TF_ROUND(24)
    x0 += k2; x1 += k0 + 2u;
    TF_ROUND(13) TF_ROUND(15) TF_ROUND(26) TF_ROUND(6)
    x0 += k0; x1 += k1 + 3u;
    TF_ROUND(17) TF_ROUND(29) TF_ROUND(16) TF_ROUND(24)
    x0 += k1; x1 += k2 + 4u;
    TF_ROUND(13) TF_ROUND(15) TF_ROUND(26) TF_ROUND(6)
    x0 += k2; x1 += k0 + 5u;
    o0 = x0; o1 = x1;
}

// Fast log variant: __logf (MUFU.LG2) instead of log1pf — measured impact
// on final rel_err: 3.15e-5 -> 3.18e-5 (negligible).
__device__ __forceinline__ float jax_normal(uint32_t bits) {
    float f = __uint_as_float((bits >> 9) | 0x3F800000u) - 1.0f;
    const float lo = __uint_as_float(0xBF7FFFFFu);   // nextafter(-1, 0)
    float u = f * 2.0f + lo;
    float w = -__logf(fmaf(-u, u, 1.0f));
    float p;
    if (w < 5.0f) {
        w = w - 2.5f;
        p = 2.81022636e-08f;
        p = fmaf(p, w, 3.43273939e-07f);
        p = fmaf(p, w, -3.5233877e-06f);
        p = fmaf(p, w, -4.39150654e-06f);
        p = fmaf(p, w, 0.00021858087f);
        p = fmaf(p, w, -0.00125372503f);
        p = fmaf(p, w, -0.00417768164f);
        p = fmaf(p, w, 0.246640727f);
        p = fmaf(p, w, 1.50140941f);
    } else {
        w = sqrtf(w) - 3.0f;
        p = -0.000200214257f;
        p = fmaf(p, w, 0.000100950558f);
        p = fmaf(p, w, 0.00134934322f);
        p = fmaf(p, w, -0.00367342844f);
        p = fmaf(p, w, 0.00573950773f);
        p = fmaf(p, w, -0.0076224613f);
        p = fmaf(p, w, 0.00943887047f);
        p = fmaf(p, w, 1.00167406f);
        p = fmaf(p, w, 2.83297682f);
    }
    return 1.41421356237f * (p * u);
}

// ---------------------------------------------------------------------------
// Prep kernels
// ---------------------------------------------------------------------------
__global__ void prep_b_kernel(const float* __restrict__ W) {
    int i = blockIdx.x * blockDim.x + threadIdx.x;   // i = n*512 + k
    if (i < DIM * DIM) {
        int n = i >> 9, k = i & 511;
        g_Bhi[i] = __float2half_rn(W[k * DIM + n]);  // W_top[k][n]
    }
}

__global__ void prep_s_kernel(const float* __restrict__ W) {
    int j = threadIdx.x;   // 512 threads, 1 block
    float s = 0.0f;
    #pragma unroll 8
    for (int k = 0; k < DIM; k++)
        s += W[(DIM + k) * DIM + j];
    g_s[j] = s;
}

__global__ void prep_x_kernel(const float* __restrict__ x0) {
    int i = blockIdx.x * blockDim.x + threadIdx.x;
    float v = x0[i];
    __half h = __float2half_rn(v);
    g_hi0[i] = h;
    g_lo0[i] = __float2half_rn(v - __half2float(h));
}

// ---------------------------------------------------------------------------
// FAT kernel: CTAs [0, G_CTAS) run a half-batch GEMM for step tG;
//             CTAs [G_CTAS, FAT_CTAS) run a half-batch epilogue for step tE
// (the two halves are independent row-chains; within a launch the parts touch
//  disjoint buffer regions). tG/tE < 0 disables the respective part.
// ---------------------------------------------------------------------------
#define NCH       8                    // 512 / 64
#define TILE_SZ   16384                // 128 rows x 128 B
#define STAGE_SZ  (2 * TILE_SZ)        // Ahi, Bhi
#define BAR_OFF   (2 * STAGE_SZ)       // 65536
#define SMEM_REQ  (BAR_OFF + 64 + 1024)

__global__ void __launch_bounds__(256, 2)
step_fused(const __grid_constant__ CUtensorMap mAhi0,
           const __grid_constant__ CUtensorMap mAhi1,
           const __grid_constant__ CUtensorMap mBhi,
           int tG, int gemm_half,
           int tE, int epi_half,
           const __half* __restrict__ hi_in,
           const __half* __restrict__ lo_in,
           __half* __restrict__ hi_out,
           __half* __restrict__ lo_out,
           float* __restrict__ score,       // full buffer; halves disjoint
           float* __restrict__ fout,        // non-null only when tE == last
           const float* __restrict__ bias) {
    extern __shared__ char smem[];
    const int tid = threadIdx.x;

    if (blockIdx.x < G_CTAS) {
        // ================= GEMM part: score[H_g] = x_hi @ W_hi =============
        if (tG < 0) return;
        const uint32_t sbRaw = smem_u32(smem);
        const uint32_t base  = (sbRaw + 1023u) & ~1023u;

        const uint32_t FULL0 = base + BAR_OFF,      FULL1 = base + BAR_OFF + 8;
        const uint32_t EMPT0 = base + BAR_OFF + 16, EMPT1 = base + BAR_OFF + 24;

        const int wid = tid >> 5, lane = tid & 31;
        const int warp_m = wid & 3, warp_n = wid >> 2;
        const int m0 = gemm_half * (BATCH / 2) + (int)(blockIdx.x & 127) * 128;
        const int n0 = (int)(blockIdx.x >> 7) * 128;
        const CUtensorMap* mA = (tG & 1) ? &mAhi1 : &mAhi0;

        if (tid == 0) {
            MBARRIER_INIT(FULL0, 1);
            MBARRIER_INIT(FULL1, 1);
            MBARRIER_INIT(EMPT0, 256);
            MBARRIER_INIT(EMPT1, 256);
        }
        __syncthreads();

        float acc[2][8][4];
        #pragma unroll
        for (int mt = 0; mt < 2; mt++)
            #pragma unroll
            for (int nt = 0; nt < 8; nt++)
                #pragma unroll
                for (int q = 0; q < 4; q++) acc[mt][nt][q] = 0.0f;

        const uint32_t xorS    = (uint32_t)(lane & 7) << 4;
        const uint32_t aRowOff = (uint32_t)(warp_m * 32 + (lane & 15)) * 128u;
        const uint32_t aSub    = (uint32_t)(lane >> 4) << 4;
        const uint32_t bRowOff = (uint32_t)(warp_n * 64 + (lane & 7) +
                                            ((lane >> 4) << 3)) * 128u;
        const uint32_t bSub    = (uint32_t)((lane >> 3) & 1) << 4;

        const uint32_t stg0 = base, stg1 = base + STAGE_SZ;

        if (tid == 0) {
            MBARRIER_EXPECT_TX(FULL0, STAGE_SZ);
            tma_load_2d(stg0,           mA,    0, m0, FULL0);
            tma_load_2d(stg0 + TILE_SZ, &mBhi, 0, n0, FULL0);
        }

        #pragma unroll 1
        for (int c = 0; c < NCH; c++) {
            const int sbi = c & 1;
            const uint32_t sb = sbi ? stg1 : stg0;
            MBARRIER_WAIT_PARITY(sbi ? FULL1 : FULL0, (c >> 1) & 1);

            if (tid == 0 && c + 1 < NCH) {
                const int s2 = (c + 1) & 1, k2 = (c + 1) >> 1;
                const uint32_t sn = s2 ? stg1 : stg0;
                if (k2 > 0)
                    MBARRIER_WAIT_PARITY(s2 ? EMPT1 : EMPT0, (k2 - 1) & 1);
                MBARRIER_EXPECT_TX(s2 ? FULL1 : FULL0, STAGE_SZ);
                const int k0 = (c + 1) * 64;
                tma_load_2d(sn,           mA,    k0, m0, s2 ? FULL1 : FULL0);
                tma_load_2d(sn + TILE_SZ, &mBhi, k0, n0, s2 ? FULL1 : FULL0);
            }

            #pragma unroll
            for (int s = 0; s < 4; s++) {
                const uint32_t ka = ((uint32_t)(s * 32) + aSub) ^ xorS;
                const uint32_t kb = ((uint32_t)(s * 32) + bSub) ^ xorS;
                uint32_t ahi[2][4];
                #pragma unroll
                for (int mt = 0; mt < 2; mt++)
                    ldsm4(ahi[mt],
                          sb + aRowOff + (uint32_t)(mt * 16 * 128) + ka);
                #pragma unroll
                for (int p = 0; p < 4; p++) {
                    uint32_t bh[4];
                    ldsm4(bh, sb + TILE_SZ + bRowOff +
                              (uint32_t)(p * 16 * 128) + kb);
                    #pragma unroll
                    for (int mt = 0; mt < 2; mt++) {
                        mma16816(acc[mt][2 * p],     ahi[mt], bh);
                        mma16816(acc[mt][2 * p + 1], ahi[mt], bh + 2);
                    }
                }
            }
            MBARRIER_ARRIVE(sbi ? EMPT1 : EMPT0);
        }

        #pragma unroll
        for (int mt = 0; mt < 2; mt++)
            #pragma unroll
            for (int h = 0; h < 2; h++) {
                const int r = m0 + warp_m * 32 + mt * 16 + (lane >> 2) + h * 8;
                const size_t rowoff = (size_t)r * DIM;
                #pragma unroll
                for (int nt = 0; nt < 8; nt++) {
                    const int cl = warp_n * 64 + nt * 8 + (lane & 3) * 2;
                    *(float2*)(score + rowoff + (n0 + cl)) =
                        make_float2(acc[mt][nt][h * 2], acc[mt][nt][h * 2 + 1]);
                }
            }
    } else {
        // ================= Epilogue part (other half, step tE) =============
        if (tE < 0) return;
        float* cbias = (float*)smem;                  // 512 floats
        uint32_t* fk = (uint32_t*)(smem + 2048);

        const float tf = (float)tE;
        for (int c = tid; c < DIM; c += 256)
            cbias[c] = 0.01f * (tf * g_s[c] + bias[c]);
        if (tid == 0) {
            uint32_t a, b2;
            tf2x32(0u, 42u, 0u, (uint32_t)tE, a, b2);
            fk[0] = a; fk[1] = b2;
        }
        __syncthreads();

        const uint32_t fk1 = fk[0], fk2 = fk[1];
        const float S2B = sqrtf(2.0f * 0.01f);

        const size_t base = (size_t)epi_half * HALF_ELEMS +
                            (size_t)(blockIdx.x - G_CTAS) * 2048 +
                            (size_t)tid * 8;
        const int c0 = (int)(base & 511u);

        const float4 s0 = *(const float4*)(score + base);
        const float4 s1 = *(const float4*)(score + base + 4);
        const uint4 hb = *(const uint4*)(hi_in + base);
        const uint4 lb = *(const uint4*)(lo_in + base);

        float xo[8];
        {
            const uint32_t* hp = &hb.x;
            const uint32_t* lp = &lb.x;
            #pragma unroll
            for (int q = 0; q < 4; q++) {
                float2 h2 = __half22float2(*(const __half2*)&hp[q]);
                float2 l2 = __half22float2(*(const __half2*)&lp[q]);
                xo[2 * q]     = h2.x + l2.x;
                xo[2 * q + 1] = h2.y + l2.y;
            }
        }

        float xn[8];
        const float* sp0 = &s0.x;
        const float* sp1 = &s1.x;
        #pragma unroll
        for (int e = 0; e < 8; e++) {
            uint32_t w0, w1;
            tf2x32(fk1, fk2, 0u, (uint32_t)base + (uint32_t)e, w0, w1);
            float sc = (e < 4) ? sp0[e] : sp1[e - 4];
            xn[e] = xo[e] + 0.01f * sc + cbias[c0 + e]
                    + S2B * jax_normal(w0 ^ w1);
        }

        uint4 ho, lo;
        uint32_t* hop = &ho.x;
        uint32_t* lop = &lo.x;
        #pragma unroll
        for (int q = 0; q < 4; q++) {
            __half2 hh = __floats2half2_rn(xn[2 * q], xn[2 * q + 1]);
            float r0 = xn[2 * q]     - __low2float(hh);
            float r1 = xn[2 * q + 1] - __high2float(hh);
            __half2 ll = __floats2half2_rn(r0, r1);
            hop[q] = *(uint32_t*)&hh;
            lop[q] = *(uint32_t*)&ll;
        }
        *(uint4*)(hi_out + base) = ho;
        *(uint4*)(lo_out + base) = lo;
        if (fout) {
            *(float4*)(fout + base)     = make_float4(xn[0], xn[1], xn[2], xn[3]);
            *(float4*)(fout + base + 4) = make_float4(xn[4], xn[5], xn[6], xn[7]);
        }
    }
}

// ---------------------------------------------------------------------------
// Host side
// ---------------------------------------------------------------------------
typedef CUresult (*PFN_encode)(CUtensorMap*, CUtensorMapDataType, cuuint32_t,
                               void*, const cuuint64_t*, const cuuint64_t*,
                               const cuuint32_t*, const cuuint32_t*,
                               CUtensorMapInterleave, CUtensorMapSwizzle,
                               CUtensorMapL2promotion, CUtensorMapFloatOOBfill);

static void make_map(PFN_encode enc, CUtensorMap* m, void* ptr,
                     uint64_t d0, uint64_t d1) {
    cuuint64_t dims[2] = {d0, d1};
    cuuint64_t strides[1] = {d0 * 2};            // row stride in bytes (fp16)
    cuuint32_t box[2] = {64, 128};               // 64 halves = 128 B inner
    cuuint32_t es[2] = {1, 1};
    enc(m, CU_TENSOR_MAP_DATA_TYPE_FLOAT16, 2, ptr, dims, strides, box, es,
        CU_TENSOR_MAP_INTERLEAVE_NONE, CU_TENSOR_MAP_SWIZZLE_128B,
        CU_TENSOR_MAP_L2_PROMOTION_L2_128B, CU_TENSOR_MAP_FLOAT_OOB_FILL_NONE);
}

extern "C" void kernel_launch(void* const* d_in, const int* in_sizes, int n_in,
                              void* d_out, int out_size) {
    const float* x0 = (const float*)d_in[0];   // (32768, 512)
    const float* W  = (const float*)d_in[1];   // (1024, 512)
    const float* b  = (const float*)d_in[2];   // (512,)
    float* out = (float*)d_out;

    void *hi0, *lo0, *hi1, *lo1, *bhi, *scr;
    cudaGetSymbolAddress(&hi0, g_hi0);
    cudaGetSymbolAddress(&lo0, g_lo0);
    cudaGetSymbolAddress(&hi1, g_hi1);
    cudaGetSymbolAddress(&lo1, g_lo1);
    cudaGetSymbolAddress(&bhi, g_Bhi);
    cudaGetSymbolAddress(&scr, g_score);

    void* fp = nullptr;
    cudaDriverEntryPointQueryResult qr;
    cudaGetDriverEntryPointByVersion("cuTensorMapEncodeTiled", &fp, 12000,
                                     cudaEnableDefault, &qr);
    PFN_encode enc = (PFN_encode)fp;

    CUtensorMap mAhi0, mAhi1, mBhi;
    make_map(enc, &mAhi0, hi0, DIM, BATCH);
    make_map(enc, &mAhi1, hi1, DIM, BATCH);
    make_map(enc, &mBhi,  bhi, DIM, DIM);

    cudaFuncSetAttribute(step_fused,
                         cudaFuncAttributeMaxDynamicSharedMemorySize, SMEM_REQ);

    prep_b_kernel<<<(DIM * DIM + 255) / 256, 256>>>(W);
    prep_s_kernel<<<1, DIM>>>(W);
    prep_x_kernel<<<NTOT / 256, 256>>>(x0);

    __half* hi[2] = {(__half*)hi0, (__half*)hi1};
    __half* lo[2] = {(__half*)lo0, (__half*)lo1};
    float* score = (float*)scr;

    for (int t = 0; t < NUM_STEPS; t++) {
        // Launch A(t): GEMM(H0, t)  ||  Epilogue(H1, t-1)
        {
            int te = t - 1;
            int pe = te & 1;
            const __half* hin = (te >= 0) ? hi[pe] : hi[0];
            const __half* lin = (te >= 0) ? lo[pe] : lo[0];
            __half* hout = (te >= 0) ? hi[pe ^ 1] : hi[1];
            __half* lout = (te >= 0) ? lo[pe ^ 1] : lo[1];
            step_fused<<<FAT_CTAS, 256, SMEM_REQ>>>(
                mAhi0, mAhi1, mBhi, t, 0, te, 1,
                hin, lin, hout, lout, score, nullptr, b);
        }
        // Launch B(t): GEMM(H1, t)  ||  Epilogue(H0, t)
        {
            int te = t;
            int pe = te & 1;
            float* fo = (te == NUM_STEPS - 1) ? out : nullptr;
            step_fused<<<FAT_CTAS, 256, SMEM_REQ>>>(
                mAhi0, mAhi1, mBhi, t, 1, te, 0,
                hi[pe], lo[pe], hi[pe ^ 1], lo[pe ^ 1], score, fo, b);
        }
    }
    // Tail: Epilogue(H1, 99) only
    {
        int te = NUM_STEPS - 1;
        int pe = te & 1;
        step_fused<<<FAT_CTAS, 256, SMEM_REQ>>>(
            mAhi0, mAhi1, mBhi, -1, 0, te, 1,
            hi[pe], lo[pe], hi[pe ^ 1], lo[pe ^ 1], score, out, b);
    }
}